// round 11
// baseline (speedup 1.0000x reference)
#include <cuda_runtime.h>
#include <cstdint>
#include <cmath>

// ── problem constants ──────────────────────────────────────────────────
#define NUM_E 8
#define TT 16384
#define DD 2048
#define HH 1024

// ── tiling ─────────────────────────────────────────────────────────────
#define BM 128
#define BK 32
#define NTHREADS 512
#define TILEA 16384            // BM x BK floats, 128B swizzled rows

// ── scratch (allocation-free rule: __device__ globals) ─────────────────
__device__ float g_w1[(size_t)NUM_E * HH * DD];  // tf32-rounded w1
__device__ float g_w3[(size_t)NUM_E * HH * DD];  // tf32-rounded w3
__device__ float g_w2[(size_t)NUM_E * DD * HH];  // tf32-rounded w2
__device__ float g_h [(size_t)TT * HH];          // silu(x@w1^T)*(x@w3^T), tf32-rounded

// ── PTX helpers ────────────────────────────────────────────────────────
__device__ __forceinline__ uint32_t f2tf32(float x) {
    uint32_t r;
    asm("cvt.rna.tf32.f32 %0, %1;" : "=r"(r) : "f"(x));
    return r;
}
__device__ __forceinline__ uint32_t rr_tf32(uint32_t bits) {
    return f2tf32(__uint_as_float(bits));
}
__device__ __forceinline__ void cpa16(uint32_t dst, const void* src) {
    asm volatile("cp.async.cg.shared.global [%0], [%1], 16;"
                 :: "r"(dst), "l"(src));
}
__device__ __forceinline__ void cpa_commit() {
    asm volatile("cp.async.commit_group;" ::: "memory");
}
template<int N>
__device__ __forceinline__ void cpa_wait() {
    asm volatile("cp.async.wait_group %0;" :: "n"(N) : "memory");
}
__device__ __forceinline__ void mma_tf32(float c[4], const uint32_t a[4],
                                         uint32_t b0, uint32_t b1) {
    asm volatile(
        "mma.sync.aligned.m16n8k8.row.col.f32.tf32.tf32.f32 "
        "{%0,%1,%2,%3}, {%4,%5,%6,%7}, {%8,%9}, {%0,%1,%2,%3};\n"
        : "+f"(c[0]), "+f"(c[1]), "+f"(c[2]), "+f"(c[3])
        : "r"(a[0]), "r"(a[1]), "r"(a[2]), "r"(a[3]), "r"(b0), "r"(b1));
}
__device__ __forceinline__ uint32_t smem_u32(const void* p) {
    uint32_t a;
    asm("{ .reg .u64 t; cvta.to.shared.u64 t, %1; cvt.u32.u64 %0, t; }"
        : "=r"(a) : "l"(p));
    return a;
}
// SW128 swizzled float index within an Rx32-float tile (128B rows)
__device__ __forceinline__ uint32_t swz(int r, int c) {
    return (uint32_t)(r * 32 + (c ^ ((r & 7) << 2)));
}

// ── fused rounding of the three weight tensors (one launch) ────────────
__global__ void __launch_bounds__(256)
round_w3x(const float4* __restrict__ s1, float4* __restrict__ d1,
          const float4* __restrict__ s2, float4* __restrict__ d2,
          const float4* __restrict__ s3, float4* __restrict__ d3, int n4) {
    auto rnd = [](float4 v) {
        v.x = __uint_as_float(f2tf32(v.x));
        v.y = __uint_as_float(f2tf32(v.y));
        v.z = __uint_as_float(f2tf32(v.z));
        v.w = __uint_as_float(f2tf32(v.w));
        return v;
    };
    for (int i = blockIdx.x * blockDim.x + threadIdx.x; i < 3 * n4;
         i += gridDim.x * blockDim.x) {
        if (i < n4)            d1[i]          = rnd(s1[i]);
        else if (i < 2 * n4)   d2[i - n4]     = rnd(s2[i - n4]);
        else                   d3[i - 2 * n4] = rnd(s3[i - 2 * n4]);
    }
}

// ── fused grouped GEMM, mma.sync tf32, 16 warps (4m x 4n) ──────────────
// PHASE 1: BN=128, warp tile 32x32 DUAL: D1=x@w1^T, D3=x@w3^T;
//          h = silu(D1)*D3 -> g_h (x tf32-rounded in-kernel on A frags)
// PHASE 2: BN=256, warp tile 32x64: out = h@w2^T -> Dout
template<int PHASE, int S>
__global__ void __launch_bounds__(NTHREADS, 1)
moe_mm(const float* __restrict__ Xin, const int* __restrict__ counts,
       float* __restrict__ Dout)
{
    extern __shared__ float fsm[];
    const uint32_t sb = smem_u32(fsm);
    const int tid  = threadIdx.x;
    const int lane = tid & 31;
    const int wid  = tid >> 5;
    const int wm   = wid & 3;          // 4 warps along M (32 rows each)
    const int wn   = wid >> 2;         // 4 warps along N

    constexpr int K     = (PHASE == 1) ? DD : HH;
    constexpr int NW    = (PHASE == 1) ? HH : DD;
    constexpr int NKT   = K / BK;
    constexpr int NT    = (PHASE == 1) ? 4 : 8;      // 8-col n-tiles per warp
    constexpr int BN    = NT * 8 * 4;                // 128 / 256
    constexpr int TILEB = BN * 128;                  // bytes per B stage

    const int m0 = blockIdx.y * BM;
    const int n0 = blockIdx.x * BN;

    // expert lookup (BM divides each group size)
    int e = 0, gb = 0;
    while (e < NUM_E - 1) { int c = counts[e]; if (m0 < gb + c) break; gb += c; e++; }

    const float* A  = ((PHASE == 1) ? Xin : g_h) + (size_t)m0 * K;
    const float* B0 = ((PHASE == 1) ? g_w1 : g_w2) + (size_t)e * NW * K + (size_t)n0 * K;
    const float* B1 = g_w3 + (size_t)e * NW * K + (size_t)n0 * K;   // PHASE 1 only

    const uint32_t sA  = sb;
    const uint32_t sB0 = sb + S * TILEA;
    const uint32_t sB1 = sB0 + S * TILEB;            // phase 1 only
    const uint32_t* uA  = (const uint32_t*)fsm;
    const uint32_t* uB0 = uA + (S * TILEA) / 4;
    const uint32_t* uB1 = uB0 + (S * TILEB) / 4;

    auto load_stage = [&](int p) {
        const int s = p % S;
#pragma unroll
        for (int i = 0; i < 2; i++) {                 // A: 1024 x 16B chunks
            const int idx = tid + i * NTHREADS;
            const int row = idx >> 3, ch = idx & 7;
            uint32_t o  = (uint32_t)(row * 128 + ch * 16);
            uint32_t so = o ^ ((o >> 3) & 0x70);
            cpa16(sA + s * TILEA + so, A + (size_t)row * K + (size_t)p * BK + ch * 4);
        }
#pragma unroll
        for (int i = 0; i < BN / 64; i++) {           // B0: BN*8 chunks
            const int idx = tid + i * NTHREADS;
            const int row = idx >> 3, ch = idx & 7;
            uint32_t o  = (uint32_t)(row * 128 + ch * 16);
            uint32_t so = o ^ ((o >> 3) & 0x70);
            cpa16(sB0 + s * TILEB + so, B0 + (size_t)row * K + (size_t)p * BK + ch * 4);
        }
        if (PHASE == 1) {
#pragma unroll
            for (int i = 0; i < 2; i++) {             // B1: 1024 chunks
                const int idx = tid + i * NTHREADS;
                const int row = idx >> 3, ch = idx & 7;
                uint32_t o  = (uint32_t)(row * 128 + ch * 16);
                uint32_t so = o ^ ((o >> 3) & 0x70);
                cpa16(sB1 + s * TILEB + so, B1 + (size_t)row * K + (size_t)p * BK + ch * 4);
            }
        }
    };

    float acc0[2][NT][4];                      // 32-row warp tile: 2 m-tiles
    float acc1[PHASE == 1 ? 2 : 1][PHASE == 1 ? NT : 1][4];
#pragma unroll
    for (int mt = 0; mt < 2; mt++)
#pragma unroll
        for (int nt = 0; nt < NT; nt++)
#pragma unroll
            for (int i = 0; i < 4; i++) {
                acc0[mt][nt][i] = 0.f;
                if (PHASE == 1) acc1[mt][nt][i] = 0.f;
            }

    uint32_t fa[2][2][4];                      // A frags, double-buffered
    uint32_t fb0[NT][2];                       // B0 frags, single-buffered
    uint32_t fb1[PHASE == 1 ? NT : 1][2];      // B1 frags, single-buffered

    const int rA = wm * 32 + (lane >> 2);
    const int rB = wn * (NT * 8) + (lane >> 2);
    const int kl = lane & 3;

    auto ldA = [&](int buf, const uint32_t* p, int ks) {
        const int kk = ks * 8 + kl;
#pragma unroll
        for (int mt = 0; mt < 2; mt++) {
            const int r = rA + mt * 16;
            uint32_t v0 = p[swz(r, kk)],     v1 = p[swz(r + 8, kk)];
            uint32_t v2 = p[swz(r, kk + 4)], v3 = p[swz(r + 8, kk + 4)];
            if (PHASE == 1) { v0 = rr_tf32(v0); v1 = rr_tf32(v1);
                              v2 = rr_tf32(v2); v3 = rr_tf32(v3); }
            fa[buf][mt][0] = v0; fa[buf][mt][1] = v1;
            fa[buf][mt][2] = v2; fa[buf][mt][3] = v3;
        }
    };
    auto ldB = [&](const uint32_t* p0, const uint32_t* p1, int ks) {
        const int kk = ks * 8 + kl;
#pragma unroll
        for (int nt = 0; nt < NT; nt++) {
            const int c = rB + nt * 8;
            fb0[nt][0] = p0[swz(c, kk)];
            fb0[nt][1] = p0[swz(c, kk + 4)];
        }
        if (PHASE == 1) {
#pragma unroll
            for (int nt = 0; nt < NT; nt++) {
                const int c = rB + nt * 8;
                fb1[nt][0] = p1[swz(c, kk)];
                fb1[nt][1] = p1[swz(c, kk + 4)];
            }
        }
    };
    auto mma_all = [&](int buf) {
#pragma unroll
        for (int nt = 0; nt < NT; nt++)
#pragma unroll
            for (int mt = 0; mt < 2; mt++) {
                mma_tf32(acc0[mt][nt], fa[buf][mt], fb0[nt][0], fb0[nt][1]);
                if (PHASE == 1)
                    mma_tf32(acc1[mt][nt], fa[buf][mt], fb1[nt][0], fb1[nt][1]);
            }
    };

    // ── prologue ───────────────────────────────────────────────────────
#pragma unroll
    for (int p = 0; p < S - 1; p++) { load_stage(p); cpa_commit(); }
    cpa_wait<S - 2>();
    __syncthreads();
    ldA(0, uA, 0);

    // ── mainloop: one sync per k-tile ──────────────────────────────────
    for (int kt = 0; kt < NKT; kt++) {
        const int s = kt % S;
        const uint32_t* cA  = uA  + (s * TILEA) / 4;
        const uint32_t* cB0 = uB0 + (s * TILEB) / 4;
        const uint32_t* cB1 = uB1 + (s * TILEB) / 4;
#pragma unroll
        for (int ks = 0; ks < 4; ks++) {
            const int cur = ks & 1, nxt = cur ^ 1;
            if (ks == 0) {
                if (kt + S - 1 < NKT) load_stage(kt + S - 1);
                cpa_commit();
            }
            ldB(cB0, cB1, ks);                 // single-buffered B frags
            if (ks < 3) {
                ldA(nxt, cA, ks + 1);
                mma_all(cur);
            } else {
                mma_all(cur);
                if (kt + 1 < NKT) {
                    cpa_wait<S - 2>();
                    __syncthreads();
                    ldA(nxt, uA + (((kt + 1) % S) * TILEA) / 4, 0);
                }
            }
        }
    }

    // ── epilogue ───────────────────────────────────────────────────────
#pragma unroll
    for (int mt = 0; mt < 2; mt++) {
        const int rbase = m0 + wm * 32 + mt * 16 + (lane >> 2);
#pragma unroll
        for (int nt = 0; nt < NT; nt++) {
            const int c = n0 + wn * (NT * 8) + nt * 8 + (lane & 3) * 2;
#pragma unroll
            for (int h2 = 0; h2 < 2; h2++) {
                const int row = rbase + h2 * 8;
                if (PHASE == 1) {
                    const float d1a = acc0[mt][nt][h2 * 2];
                    const float d1b = acc0[mt][nt][h2 * 2 + 1];
                    const float d3a = acc1[mt][nt][h2 * 2];
                    const float d3b = acc1[mt][nt][h2 * 2 + 1];
                    float2 v;
                    v.x = __uint_as_float(f2tf32(d1a / (1.f + __expf(-d1a)) * d3a));
                    v.y = __uint_as_float(f2tf32(d1b / (1.f + __expf(-d1b)) * d3b));
                    *(float2*)&g_h[(size_t)row * HH + c] = v;
                } else {
                    *(float2*)&Dout[(size_t)row * DD + c] =
                        make_float2(acc0[mt][nt][h2 * 2], acc0[mt][nt][h2 * 2 + 1]);
                }
            }
        }
    }
}

// ── host launch ────────────────────────────────────────────────────────
extern "C" void kernel_launch(void* const* d_in, const int* in_sizes, int n_in,
                              void* d_out, int out_size) {
    const float* x   = (const float*)d_in[0];
    const int*   cnt = (const int*)  d_in[1];
    const float* w1  = (const float*)d_in[2];
    const float* w2  = (const float*)d_in[3];
    const float* w3  = (const float*)d_in[4];
    float* out = (float*)d_out;

    void *pw1, *pw3, *pw2;
    cudaGetSymbolAddress(&pw1, g_w1);
    cudaGetSymbolAddress(&pw3, g_w3);
    cudaGetSymbolAddress(&pw2, g_w2);

    constexpr int S1 = 4, S2 = 4;
    const int smem1 = 3 * S1 * TILEA;               // 196608 B (A + B0 + B1)
    const int smem2 = S2 * (TILEA + 256 * 128);     // 196608 B (A + wide B0)
    cudaFuncSetAttribute(moe_mm<1, S1>, cudaFuncAttributeMaxDynamicSharedMemorySize, smem1);
    cudaFuncSetAttribute(moe_mm<2, S2>, cudaFuncAttributeMaxDynamicSharedMemorySize, smem2);

    // round the three weight tensors to tf32 (rna) in ONE launch; x is
    // rounded in-kernel on the A fragments (bit-identical numerics).
    const int n4 = NUM_E * HH * DD / 4;
    round_w3x<<<2048, 256>>>((const float4*)w1, (float4*)pw1,
                             (const float4*)w3, (float4*)pw3,
                             (const float4*)w2, (float4*)pw2, n4);

    moe_mm<1, S1><<<dim3(HH / 128, TT / BM), NTHREADS, smem1>>>(x, cnt, nullptr); // (8,128)
    moe_mm<2, S2><<<dim3(DD / 256, TT / BM), NTHREADS, smem2>>>(nullptr, cnt, out); // (8,128)
}

// round 16
// speedup vs baseline: 1.3160x; 1.3160x over previous
#include <cuda_runtime.h>
#include <cuda_fp16.h>
#include <cstdint>
#include <cmath>

// ── problem constants ──────────────────────────────────────────────────
#define NUM_E 8
#define TT 16384
#define DD 2048
#define HH 1024
#define BM 128
#define NTHREADS 256

// ── scratch (allocation-free rule: __device__ globals) ─────────────────
__device__ float  g_w1[(size_t)NUM_E * HH * DD];   // tf32-rounded w1
__device__ float  g_w3[(size_t)NUM_E * HH * DD];   // tf32-rounded w3
__device__ __half g_w2h[(size_t)NUM_E * DD * HH];  // fp16-rounded w2
__device__ __half g_h  [(size_t)TT * HH];          // h = silu(d1)*d3, fp16

// ── PTX helpers ────────────────────────────────────────────────────────
__device__ __forceinline__ uint32_t f2tf32(float x) {
    uint32_t r;
    asm("cvt.rna.tf32.f32 %0, %1;" : "=r"(r) : "f"(x));
    return r;
}
__device__ __forceinline__ uint32_t rr_tf32(uint32_t bits) {
    return f2tf32(__uint_as_float(bits));
}
__device__ __forceinline__ void cpa16(uint32_t dst, const void* src) {
    asm volatile("cp.async.cg.shared.global [%0], [%1], 16;"
                 :: "r"(dst), "l"(src));
}
__device__ __forceinline__ void cpa_commit() {
    asm volatile("cp.async.commit_group;" ::: "memory");
}
template<int N>
__device__ __forceinline__ void cpa_wait() {
    asm volatile("cp.async.wait_group %0;" :: "n"(N) : "memory");
}
__device__ __forceinline__ void mma_tf32(float c[4], const uint32_t a[4],
                                         uint32_t b0, uint32_t b1) {
    asm volatile(
        "mma.sync.aligned.m16n8k8.row.col.f32.tf32.tf32.f32 "
        "{%0,%1,%2,%3}, {%4,%5,%6,%7}, {%8,%9}, {%0,%1,%2,%3};\n"
        : "+f"(c[0]), "+f"(c[1]), "+f"(c[2]), "+f"(c[3])
        : "r"(a[0]), "r"(a[1]), "r"(a[2]), "r"(a[3]), "r"(b0), "r"(b1));
}
__device__ __forceinline__ void mma_f16(float c[4], const uint32_t a[4],
                                        uint32_t b0, uint32_t b1) {
    asm volatile(
        "mma.sync.aligned.m16n8k16.row.col.f32.f16.f16.f32 "
        "{%0,%1,%2,%3}, {%4,%5,%6,%7}, {%8,%9}, {%0,%1,%2,%3};\n"
        : "+f"(c[0]), "+f"(c[1]), "+f"(c[2]), "+f"(c[3])
        : "r"(a[0]), "r"(a[1]), "r"(a[2]), "r"(a[3]), "r"(b0), "r"(b1));
}
__device__ __forceinline__ uint32_t smem_u32(const void* p) {
    uint32_t a;
    asm("{ .reg .u64 t; cvta.to.shared.u64 t, %1; cvt.u32.u64 %0, t; }"
        : "=r"(a) : "l"(p));
    return a;
}
// SW128 swizzled u32 index within an Rx32-u32 tile (128B rows)
__device__ __forceinline__ uint32_t swz(int r, int c) {
    return (uint32_t)(r * 32 + (c ^ ((r & 7) << 2)));
}

// ── fused rounding: w1,w3 -> tf32 fp32; w2 -> fp16 (one launch) ────────
__global__ void __launch_bounds__(256)
round_pack(const float4* __restrict__ s1, float4* __restrict__ d1,
           const float4* __restrict__ s3, float4* __restrict__ d3,
           const float4* __restrict__ s2, uint2* __restrict__ d2h, int n4) {
    auto rnd = [](float4 v) {
        v.x = __uint_as_float(f2tf32(v.x));
        v.y = __uint_as_float(f2tf32(v.y));
        v.z = __uint_as_float(f2tf32(v.z));
        v.w = __uint_as_float(f2tf32(v.w));
        return v;
    };
    for (int i = blockIdx.x * blockDim.x + threadIdx.x; i < 3 * n4;
         i += gridDim.x * blockDim.x) {
        if (i < n4)           d1[i]       = rnd(s1[i]);
        else if (i < 2 * n4)  d3[i - n4]  = rnd(s3[i - n4]);
        else {
            const float4 v = s2[i - 2 * n4];
            __half2 lo = __floats2half2_rn(v.x, v.y);
            __half2 hi = __floats2half2_rn(v.z, v.w);
            uint2 o;
            o.x = *(uint32_t*)&lo;
            o.y = *(uint32_t*)&hi;
            d2h[i - 2 * n4] = o;
        }
    }
}

// ── PHASE 1: tf32 dual-B GEMM, BK=32, S=4 stages ───────────────────────
// D1 = x@w1^T, D3 = x@w3^T; h = silu(D1)*D3 -> g_h (fp16)
// 8 warps as 2(m) x 4(n); warp tile 64x32 per output matrix.
#define P1_S 4
#define P1_TILE 16384   // 128 rows x 32 floats (128B swizzled rows)
__global__ void __launch_bounds__(NTHREADS, 1)
moe_p1(const float* __restrict__ Xin, const int* __restrict__ counts)
{
    extern __shared__ float fsm[];
    const uint32_t sb = smem_u32(fsm);
    const int tid  = threadIdx.x;
    const int lane = tid & 31;
    const int wid  = tid >> 5;
    const int wm   = wid & 1;
    const int wn   = wid >> 1;

    constexpr int K = DD, NKT = K / 32;

    const int m0 = blockIdx.y * BM;
    const int n0 = blockIdx.x * 128;

    int e = 0, gb = 0;
    while (e < NUM_E - 1) { int c = counts[e]; if (m0 < gb + c) break; gb += c; e++; }

    const float* A  = Xin + (size_t)m0 * K;
    const float* B0 = g_w1 + (size_t)e * HH * K + (size_t)n0 * K;
    const float* B1 = g_w3 + (size_t)e * HH * K + (size_t)n0 * K;

    const uint32_t sA  = sb;
    const uint32_t sB0 = sb + P1_S * P1_TILE;
    const uint32_t sB1 = sB0 + P1_S * P1_TILE;
    const uint32_t* uA  = (const uint32_t*)fsm;
    const uint32_t* uB0 = uA + (P1_S * P1_TILE) / 4;
    const uint32_t* uB1 = uB0 + (P1_S * P1_TILE) / 4;

    auto load_stage = [&](int p) {
        const int s = p % P1_S;
#pragma unroll
        for (int i = 0; i < 4; i++) {
            const int idx = tid + i * NTHREADS;     // 0..1023
            const int row = idx >> 3, ch = idx & 7;
            uint32_t o  = (uint32_t)(row * 128 + ch * 16);
            uint32_t so = o ^ ((o >> 3) & 0x70);
            const size_t go = (size_t)row * K + (size_t)p * 32 + ch * 4;
            cpa16(sA  + s * P1_TILE + so, A  + go);
            cpa16(sB0 + s * P1_TILE + so, B0 + go);
            cpa16(sB1 + s * P1_TILE + so, B1 + go);
        }
    };

    float acc0[4][4][4], acc1[4][4][4];
#pragma unroll
    for (int mt = 0; mt < 4; mt++)
#pragma unroll
        for (int nt = 0; nt < 4; nt++)
#pragma unroll
            for (int i = 0; i < 4; i++) { acc0[mt][nt][i] = 0.f; acc1[mt][nt][i] = 0.f; }

    uint32_t fa[2][4][4], fb0[2][4][2], fb1[2][4][2];

    const int rA = wm * 64 + (lane >> 2);
    const int rB = wn * 32 + (lane >> 2);
    const int kl = lane & 3;

    auto ldA = [&](int buf, const uint32_t* p, int ks) {
        const int kk = ks * 8 + kl;
#pragma unroll
        for (int mt = 0; mt < 4; mt++) {
            const int r = rA + mt * 16;
            fa[buf][mt][0] = rr_tf32(p[swz(r, kk)]);
            fa[buf][mt][1] = rr_tf32(p[swz(r + 8, kk)]);
            fa[buf][mt][2] = rr_tf32(p[swz(r, kk + 4)]);
            fa[buf][mt][3] = rr_tf32(p[swz(r + 8, kk + 4)]);
        }
    };
    auto ldB = [&](int buf, const uint32_t* p0, const uint32_t* p1, int ks) {
        const int kk = ks * 8 + kl;
#pragma unroll
        for (int nt = 0; nt < 4; nt++) {
            const int c = rB + nt * 8;
            fb0[buf][nt][0] = p0[swz(c, kk)];
            fb0[buf][nt][1] = p0[swz(c, kk + 4)];
            fb1[buf][nt][0] = p1[swz(c, kk)];
            fb1[buf][nt][1] = p1[swz(c, kk + 4)];
        }
    };
    auto mma_all = [&](int buf) {
#pragma unroll
        for (int nt = 0; nt < 4; nt++)
#pragma unroll
            for (int mt = 0; mt < 4; mt++) {
                mma_tf32(acc0[mt][nt], fa[buf][mt], fb0[buf][nt][0], fb0[buf][nt][1]);
                mma_tf32(acc1[mt][nt], fa[buf][mt], fb1[buf][nt][0], fb1[buf][nt][1]);
            }
    };

#pragma unroll
    for (int p = 0; p < P1_S - 1; p++) { load_stage(p); cpa_commit(); }
    cpa_wait<P1_S - 2>();
    __syncthreads();
    ldA(0, uA, 0);
    ldB(0, uB0, uB1, 0);

    for (int kt = 0; kt < NKT; kt++) {
        const int s = kt % P1_S;
        const uint32_t* cA  = uA  + (s * P1_TILE) / 4;
        const uint32_t* cB0 = uB0 + (s * P1_TILE) / 4;
        const uint32_t* cB1 = uB1 + (s * P1_TILE) / 4;
#pragma unroll
        for (int ks = 0; ks < 4; ks++) {
            const int cur = ks & 1, nxt = cur ^ 1;
            if (ks == 0) {
                if (kt + P1_S - 1 < NKT) load_stage(kt + P1_S - 1);
                cpa_commit();
            }
            if (ks < 3) {
                ldA(nxt, cA, ks + 1);
                ldB(nxt, cB0, cB1, ks + 1);
                mma_all(cur);
            } else {
                mma_all(cur);
                if (kt + 1 < NKT) {
                    cpa_wait<P1_S - 2>();
                    __syncthreads();
                    const int sn = (kt + 1) % P1_S;
                    ldA(nxt, uA + (sn * P1_TILE) / 4, 0);
                    ldB(nxt, uB0 + (sn * P1_TILE) / 4, uB1 + (sn * P1_TILE) / 4, 0);
                }
            }
        }
    }

    // epilogue: h = silu(d1)*d3, fp16
#pragma unroll
    for (int mt = 0; mt < 4; mt++) {
        const int rbase = m0 + wm * 64 + mt * 16 + (lane >> 2);
#pragma unroll
        for (int nt = 0; nt < 4; nt++) {
            const int c = n0 + wn * 32 + nt * 8 + (lane & 3) * 2;
#pragma unroll
            for (int h2 = 0; h2 < 2; h2++) {
                const int row = rbase + h2 * 8;
                const float d1a = acc0[mt][nt][h2 * 2];
                const float d1b = acc0[mt][nt][h2 * 2 + 1];
                const float d3a = acc1[mt][nt][h2 * 2];
                const float d3b = acc1[mt][nt][h2 * 2 + 1];
                const float va = d1a / (1.f + __expf(-d1a)) * d3a;
                const float vb = d1b / (1.f + __expf(-d1b)) * d3b;
                *(__half2*)&g_h[(size_t)row * HH + c] = __floats2half2_rn(va, vb);
            }
        }
    }
}

// ── PHASE 2: fp16 GEMM, BK=64 (4 K16-steps), BN=256, S=4 ───────────────
// out = h @ w2^T -> Dout (fp32). 8 warps 2(m) x 4(n); warp tile 64x64.
#define P2_S 4
#define P2_TA 16384   // A: 128 rows x 64 halfs (128B rows)
#define P2_TB 32768   // B: 256 rows x 64 halfs
__global__ void __launch_bounds__(NTHREADS, 1)
moe_p2(const int* __restrict__ counts, float* __restrict__ Dout)
{
    extern __shared__ float fsm[];
    const uint32_t sb = smem_u32(fsm);
    const int tid  = threadIdx.x;
    const int lane = tid & 31;
    const int wid  = tid >> 5;
    const int wm   = wid & 1;
    const int wn   = wid >> 1;

    constexpr int K = HH, NKT = K / 64;

    const int m0 = blockIdx.y * BM;
    const int n0 = blockIdx.x * 256;

    int e = 0, gb = 0;
    while (e < NUM_E - 1) { int c = counts[e]; if (m0 < gb + c) break; gb += c; e++; }

    const __half* A = g_h + (size_t)m0 * K;
    const __half* B = g_w2h + (size_t)e * DD * K + (size_t)n0 * K;

    const uint32_t sA = sb;
    const uint32_t sB = sb + P2_S * P2_TA;
    const uint32_t* uA = (const uint32_t*)fsm;
    const uint32_t* uB = uA + (P2_S * P2_TA) / 4;

    auto load_stage = [&](int p) {
        const int s = p % P2_S;
#pragma unroll
        for (int i = 0; i < 4; i++) {                 // A: 1024 x 16B chunks
            const int idx = tid + i * NTHREADS;
            const int row = idx >> 3, ch = idx & 7;
            uint32_t o  = (uint32_t)(row * 128 + ch * 16);
            uint32_t so = o ^ ((o >> 3) & 0x70);
            cpa16(sA + s * P2_TA + so, A + (size_t)row * K + (size_t)p * 64 + ch * 8);
        }
#pragma unroll
        for (int i = 0; i < 8; i++) {                 // B: 2048 x 16B chunks
            const int idx = tid + i * NTHREADS;
            const int row = idx >> 3, ch = idx & 7;
            uint32_t o  = (uint32_t)(row * 128 + ch * 16);
            uint32_t so = o ^ ((o >> 3) & 0x70);
            cpa16(sB + s * P2_TB + so, B + (size_t)row * K + (size_t)p * 64 + ch * 8);
        }
    };

    float acc[4][8][4];
#pragma unroll
    for (int mt = 0; mt < 4; mt++)
#pragma unroll
        for (int nt = 0; nt < 8; nt++)
#pragma unroll
            for (int i = 0; i < 4; i++) acc[mt][nt][i] = 0.f;

    uint32_t fa[2][4][4], fb[2][8][2];

    const int rA = wm * 64 + (lane >> 2);
    const int rB = wn * 64 + (lane >> 2);
    const int kl = lane & 3;

    // m16n8k16 fragments over 64-half rows (32 u32 granules; granule = k-pair)
    auto ldA = [&](int buf, const uint32_t* p, int ks) {
        const int kk = ks * 8 + kl;                   // u32 granule index
#pragma unroll
        for (int mt = 0; mt < 4; mt++) {
            const int r = rA + mt * 16;
            fa[buf][mt][0] = p[swz(r, kk)];           // (r,   k0:k1)
            fa[buf][mt][1] = p[swz(r + 8, kk)];       // (r+8, k0:k1)
            fa[buf][mt][2] = p[swz(r, kk + 4)];       // (r,   k8:k9)
            fa[buf][mt][3] = p[swz(r + 8, kk + 4)];   // (r+8, k8:k9)
        }
    };
    auto ldB = [&](int buf, const uint32_t* p, int ks) {
        const int kk = ks * 8 + kl;
#pragma unroll
        for (int nt = 0; nt < 8; nt++) {
            const int c = rB + nt * 8;
            fb[buf][nt][0] = p[swz(c, kk)];
            fb[buf][nt][1] = p[swz(c, kk + 4)];
        }
    };
    auto mma_all = [&](int buf) {
#pragma unroll
        for (int nt = 0; nt < 8; nt++)
#pragma unroll
            for (int mt = 0; mt < 4; mt++)
                mma_f16(acc[mt][nt], fa[buf][mt], fb[buf][nt][0], fb[buf][nt][1]);
    };

#pragma unroll
    for (int p = 0; p < P2_S - 1; p++) { load_stage(p); cpa_commit(); }
    cpa_wait<P2_S - 2>();
    __syncthreads();
    ldA(0, uA, 0);
    ldB(0, uB, 0);

    for (int kt = 0; kt < NKT; kt++) {
        const int s = kt % P2_S;
        const uint32_t* cA = uA + (s * P2_TA) / 4;
        const uint32_t* cB = uB + (s * P2_TB) / 4;
#pragma unroll
        for (int ks = 0; ks < 4; ks++) {              // 4 x K16 per 64-k tile
            const int cur = ks & 1, nxt = cur ^ 1;
            if (ks == 0) {
                if (kt + P2_S - 1 < NKT) load_stage(kt + P2_S - 1);
                cpa_commit();
            }
            if (ks < 3) {
                ldA(nxt, cA, ks + 1);
                ldB(nxt, cB, ks + 1);
                mma_all(cur);
            } else {
                mma_all(cur);
                if (kt + 1 < NKT) {
                    cpa_wait<P2_S - 2>();
                    __syncthreads();
                    const int sn = (kt + 1) % P2_S;
                    ldA(nxt, uA + (sn * P2_TA) / 4, 0);
                    ldB(nxt, uB + (sn * P2_TB) / 4, 0);
                }
            }
        }
    }

    // epilogue (fp32 out)
#pragma unroll
    for (int mt = 0; mt < 4; mt++) {
        const int rbase = m0 + wm * 64 + mt * 16 + (lane >> 2);
#pragma unroll
        for (int nt = 0; nt < 8; nt++) {
            const int c = n0 + wn * 64 + nt * 8 + (lane & 3) * 2;
#pragma unroll
            for (int h2 = 0; h2 < 2; h2++) {
                const int row = rbase + h2 * 8;
                *(float2*)&Dout[(size_t)row * DD + c] =
                    make_float2(acc[mt][nt][h2 * 2], acc[mt][nt][h2 * 2 + 1]);
            }
        }
    }
}

// ── host launch ────────────────────────────────────────────────────────
extern "C" void kernel_launch(void* const* d_in, const int* in_sizes, int n_in,
                              void* d_out, int out_size) {
    const float* x   = (const float*)d_in[0];
    const int*   cnt = (const int*)  d_in[1];
    const float* w1  = (const float*)d_in[2];
    const float* w2  = (const float*)d_in[3];
    const float* w3  = (const float*)d_in[4];
    float* out = (float*)d_out;

    void *pw1, *pw3, *pw2h;
    cudaGetSymbolAddress(&pw1,  g_w1);
    cudaGetSymbolAddress(&pw3,  g_w3);
    cudaGetSymbolAddress(&pw2h, g_w2h);

    const int smem1 = 3 * P1_S * P1_TILE;          // 196608 B
    const int smem2 = P2_S * (P2_TA + P2_TB);      // 196608 B
    cudaFuncSetAttribute(moe_p1, cudaFuncAttributeMaxDynamicSharedMemorySize, smem1);
    cudaFuncSetAttribute(moe_p2, cudaFuncAttributeMaxDynamicSharedMemorySize, smem2);

    // w1/w3 -> tf32-rounded fp32; w2 -> fp16 (rn). x rounded in-kernel.
    const int n4 = NUM_E * HH * DD / 4;
    round_pack<<<2048, 256>>>((const float4*)w1, (float4*)pw1,
                              (const float4*)w3, (float4*)pw3,
                              (const float4*)w2, (uint2*)pw2h, n4);

    moe_p1<<<dim3(HH / 128, TT / BM), NTHREADS, smem1>>>(x, cnt);        // (8,128)
    moe_p2<<<dim3(DD / 256, TT / BM), NTHREADS, smem2>>>(cnt, out);      // (8,128)
}

// round 17
// speedup vs baseline: 2.1365x; 1.6235x over previous
#include <cuda_runtime.h>
#include <cuda_fp16.h>
#include <cstdint>
#include <cmath>

// ── problem constants ──────────────────────────────────────────────────
#define NUM_E 8
#define TT 16384
#define DD 2048
#define HH 1024
#define BM 128
#define NTHREADS 256

// ── scratch (allocation-free rule: __device__ globals) ─────────────────
__device__ __half g_xh [(size_t)TT * DD];           // fp16-rounded x
__device__ __half g_w1h[(size_t)NUM_E * HH * DD];   // fp16-rounded w1
__device__ __half g_w3h[(size_t)NUM_E * HH * DD];   // fp16-rounded w3
__device__ __half g_w2h[(size_t)NUM_E * DD * HH];   // fp16-rounded w2
__device__ __half g_h  [(size_t)TT * HH];           // h = silu(d1)*d3, fp16

// ── PTX helpers ────────────────────────────────────────────────────────
__device__ __forceinline__ void cpa16(uint32_t dst, const void* src) {
    asm volatile("cp.async.cg.shared.global [%0], [%1], 16;"
                 :: "r"(dst), "l"(src));
}
__device__ __forceinline__ void cpa_commit() {
    asm volatile("cp.async.commit_group;" ::: "memory");
}
template<int N>
__device__ __forceinline__ void cpa_wait() {
    asm volatile("cp.async.wait_group %0;" :: "n"(N) : "memory");
}
__device__ __forceinline__ void mma_f16(float c[4], const uint32_t a[4],
                                        uint32_t b0, uint32_t b1) {
    asm volatile(
        "mma.sync.aligned.m16n8k16.row.col.f32.f16.f16.f32 "
        "{%0,%1,%2,%3}, {%4,%5,%6,%7}, {%8,%9}, {%0,%1,%2,%3};\n"
        : "+f"(c[0]), "+f"(c[1]), "+f"(c[2]), "+f"(c[3])
        : "r"(a[0]), "r"(a[1]), "r"(a[2]), "r"(a[3]), "r"(b0), "r"(b1));
}
__device__ __forceinline__ uint32_t smem_u32(const void* p) {
    uint32_t a;
    asm("{ .reg .u64 t; cvta.to.shared.u64 t, %1; cvt.u32.u64 %0, t; }"
        : "=r"(a) : "l"(p));
    return a;
}
// SW128 swizzled u32 index within an Rx32-u32 tile (128B rows)
__device__ __forceinline__ uint32_t swz(int r, int c) {
    return (uint32_t)(r * 32 + (c ^ ((r & 7) << 2)));
}

// ── fused fp16 rounding of x, w1, w3, w2 (one launch) ──────────────────
__global__ void __launch_bounds__(256)
round_pack(const float4* __restrict__ sx, uint2* __restrict__ dx,
           const float4* __restrict__ s1, uint2* __restrict__ d1,
           const float4* __restrict__ s3, uint2* __restrict__ d3,
           const float4* __restrict__ s2, uint2* __restrict__ d2,
           int n4x, int n4w) {
    auto cvt = [](float4 v) {
        __half2 lo = __floats2half2_rn(v.x, v.y);
        __half2 hi = __floats2half2_rn(v.z, v.w);
        uint2 o;
        o.x = *(uint32_t*)&lo;
        o.y = *(uint32_t*)&hi;
        return o;
    };
    const int total = n4x + 3 * n4w;
    for (int i = blockIdx.x * blockDim.x + threadIdx.x; i < total;
         i += gridDim.x * blockDim.x) {
        if (i < n4x) { dx[i] = cvt(sx[i]); continue; }
        const int j = i - n4x;
        if (j < n4w)           d1[j]           = cvt(s1[j]);
        else if (j < 2 * n4w)  d3[j - n4w]     = cvt(s3[j - n4w]);
        else                   d2[j - 2 * n4w] = cvt(s2[j - 2 * n4w]);
    }
}

// ── fused grouped GEMM, fp16 mma.m16n8k16, fp32 accum ──────────────────
// PHASE 1: BN=128, dual-B: D1=x@w1^T, D3=x@w3^T; h=silu(D1)*D3 -> g_h
// PHASE 2: BN=256, single-B: out = h@w2^T -> Dout (fp32)
// BK = 64 halves (128B rows). 8 warps 2(m) x 4(n); warp tile 64 x (BN/4).
#define TILEA 16384     // 128 rows x 64 halves
template<int PHASE, int S>
__global__ void __launch_bounds__(NTHREADS, 1)
moe_hmm(const int* __restrict__ counts, float* __restrict__ Dout)
{
    extern __shared__ float fsm[];
    const uint32_t sb = smem_u32(fsm);
    const int tid  = threadIdx.x;
    const int lane = tid & 31;
    const int wid  = tid >> 5;
    const int wm   = wid & 1;          // 2 warps along M (64 rows each)
    const int wn   = wid >> 1;         // 4 warps along N

    constexpr int K     = (PHASE == 1) ? DD : HH;
    constexpr int NW    = (PHASE == 1) ? HH : DD;
    constexpr int NKT   = K / 64;
    constexpr int NT    = (PHASE == 1) ? 4 : 8;      // 8-col n-tiles per warp
    constexpr int BN    = NT * 8 * 4;                // 128 / 256
    constexpr int TILEB = BN * 128;                  // bytes per B stage

    const int m0 = blockIdx.y * BM;
    const int n0 = blockIdx.x * BN;

    // expert lookup (BM divides each group size)
    int e = 0, gb = 0;
    while (e < NUM_E - 1) { int c = counts[e]; if (m0 < gb + c) break; gb += c; e++; }

    const __half* A  = ((PHASE == 1) ? g_xh : g_h) + (size_t)m0 * K;
    const __half* B0 = ((PHASE == 1) ? g_w1h : g_w2h) + (size_t)e * NW * K + (size_t)n0 * K;
    const __half* B1 = g_w3h + (size_t)e * HH * K + (size_t)n0 * K;  // PHASE 1 only

    const uint32_t sA  = sb;
    const uint32_t sB0 = sb + S * TILEA;
    const uint32_t sB1 = sB0 + S * TILEB;            // phase 1 only
    const uint32_t* uA  = (const uint32_t*)fsm;
    const uint32_t* uB0 = uA + (S * TILEA) / 4;
    const uint32_t* uB1 = uB0 + (S * TILEB) / 4;

    auto load_stage = [&](int p) {
        const int s = p % S;
#pragma unroll
        for (int i = 0; i < 4; i++) {                 // A: 1024 x 16B chunks
            const int idx = tid + i * NTHREADS;
            const int row = idx >> 3, ch = idx & 7;
            uint32_t o  = (uint32_t)(row * 128 + ch * 16);
            uint32_t so = o ^ ((o >> 3) & 0x70);
            cpa16(sA + s * TILEA + so, A + (size_t)row * K + (size_t)p * 64 + ch * 8);
        }
#pragma unroll
        for (int i = 0; i < BN / 32; i++) {           // B0: BN*8 chunks
            const int idx = tid + i * NTHREADS;
            const int row = idx >> 3, ch = idx & 7;
            uint32_t o  = (uint32_t)(row * 128 + ch * 16);
            uint32_t so = o ^ ((o >> 3) & 0x70);
            cpa16(sB0 + s * TILEB + so, B0 + (size_t)row * K + (size_t)p * 64 + ch * 8);
        }
        if (PHASE == 1) {
#pragma unroll
            for (int i = 0; i < 4; i++) {             // B1: 1024 chunks
                const int idx = tid + i * NTHREADS;
                const int row = idx >> 3, ch = idx & 7;
                uint32_t o  = (uint32_t)(row * 128 + ch * 16);
                uint32_t so = o ^ ((o >> 3) & 0x70);
                cpa16(sB1 + s * TILEB + so, B1 + (size_t)row * K + (size_t)p * 64 + ch * 8);
            }
        }
    };

    float acc0[4][NT][4];
    float acc1[PHASE == 1 ? 4 : 1][PHASE == 1 ? NT : 1][4];
#pragma unroll
    for (int mt = 0; mt < 4; mt++)
#pragma unroll
        for (int nt = 0; nt < NT; nt++)
#pragma unroll
            for (int i = 0; i < 4; i++) {
                acc0[mt][nt][i] = 0.f;
                if (PHASE == 1) acc1[mt][nt][i] = 0.f;
            }

    uint32_t fa[2][4][4];                        // A frags, double-buffered
    uint32_t fb0[2][NT][2];                      // B0 frags, double-buffered
    uint32_t fb1[2][PHASE == 1 ? NT : 1][2];     // B1 frags (phase 1)

    const int rA = wm * 64 + (lane >> 2);
    const int rB = wn * (NT * 8) + (lane >> 2);
    const int kl = lane & 3;

    // m16n8k16 fragments over 64-half rows (32 u32 granules; granule = k-pair)
    auto ldA = [&](int buf, const uint32_t* p, int ks) {
        const int kk = ks * 8 + kl;
#pragma unroll
        for (int mt = 0; mt < 4; mt++) {
            const int r = rA + mt * 16;
            fa[buf][mt][0] = p[swz(r, kk)];
            fa[buf][mt][1] = p[swz(r + 8, kk)];
            fa[buf][mt][2] = p[swz(r, kk + 4)];
            fa[buf][mt][3] = p[swz(r + 8, kk + 4)];
        }
    };
    auto ldB = [&](int buf, const uint32_t* p0, const uint32_t* p1, int ks) {
        const int kk = ks * 8 + kl;
#pragma unroll
        for (int nt = 0; nt < NT; nt++) {
            const int c = rB + nt * 8;
            fb0[buf][nt][0] = p0[swz(c, kk)];
            fb0[buf][nt][1] = p0[swz(c, kk + 4)];
        }
        if (PHASE == 1) {
#pragma unroll
            for (int nt = 0; nt < NT; nt++) {
                const int c = rB + nt * 8;
                fb1[buf][nt][0] = p1[swz(c, kk)];
                fb1[buf][nt][1] = p1[swz(c, kk + 4)];
            }
        }
    };
    auto mma_all = [&](int buf) {
#pragma unroll
        for (int nt = 0; nt < NT; nt++)
#pragma unroll
            for (int mt = 0; mt < 4; mt++) {
                mma_f16(acc0[mt][nt], fa[buf][mt], fb0[buf][nt][0], fb0[buf][nt][1]);
                if (PHASE == 1)
                    mma_f16(acc1[mt][nt], fa[buf][mt], fb1[buf][nt][0], fb1[buf][nt][1]);
            }
    };

    // ── prologue ───────────────────────────────────────────────────────
#pragma unroll
    for (int p = 0; p < S - 1; p++) { load_stage(p); cpa_commit(); }
    cpa_wait<S - 2>();
    __syncthreads();
    ldA(0, uA, 0);
    ldB(0, uB0, uB1, 0);

    // ── mainloop: one sync per 64-k tile ───────────────────────────────
    for (int kt = 0; kt < NKT; kt++) {
        const int s = kt % S;
        const uint32_t* cA  = uA  + (s * TILEA) / 4;
        const uint32_t* cB0 = uB0 + (s * TILEB) / 4;
        const uint32_t* cB1 = uB1 + (s * TILEB) / 4;
#pragma unroll
        for (int ks = 0; ks < 4; ks++) {              // 4 x K16 per 64-k tile
            const int cur = ks & 1, nxt = cur ^ 1;
            if (ks == 0) {
                if (kt + S - 1 < NKT) load_stage(kt + S - 1);
                cpa_commit();
            }
            if (ks < 3) {
                ldA(nxt, cA, ks + 1);
                ldB(nxt, cB0, cB1, ks + 1);
                mma_all(cur);
            } else {
                mma_all(cur);
                if (kt + 1 < NKT) {
                    cpa_wait<S - 2>();
                    __syncthreads();
                    const int sn = (kt + 1) % S;
                    ldA(nxt, uA + (sn * TILEA) / 4, 0);
                    ldB(nxt, uB0 + (sn * TILEB) / 4, uB1 + (sn * TILEB) / 4, 0);
                }
            }
        }
    }

    // ── epilogue ───────────────────────────────────────────────────────
#pragma unroll
    for (int mt = 0; mt < 4; mt++) {
        const int rbase = m0 + wm * 64 + mt * 16 + (lane >> 2);
#pragma unroll
        for (int nt = 0; nt < NT; nt++) {
            const int c = n0 + wn * (NT * 8) + nt * 8 + (lane & 3) * 2;
#pragma unroll
            for (int h2 = 0; h2 < 2; h2++) {
                const int row = rbase + h2 * 8;
                if (PHASE == 1) {
                    const float d1a = acc0[mt][nt][h2 * 2];
                    const float d1b = acc0[mt][nt][h2 * 2 + 1];
                    const float d3a = acc1[mt][nt][h2 * 2];
                    const float d3b = acc1[mt][nt][h2 * 2 + 1];
                    const float va = d1a / (1.f + __expf(-d1a)) * d3a;
                    const float vb = d1b / (1.f + __expf(-d1b)) * d3b;
                    *(__half2*)&g_h[(size_t)row * HH + c] = __floats2half2_rn(va, vb);
                } else {
                    *(float2*)&Dout[(size_t)row * DD + c] =
                        make_float2(acc0[mt][nt][h2 * 2], acc0[mt][nt][h2 * 2 + 1]);
                }
            }
        }
    }
}

// ── host launch ────────────────────────────────────────────────────────
extern "C" void kernel_launch(void* const* d_in, const int* in_sizes, int n_in,
                              void* d_out, int out_size) {
    const float* x   = (const float*)d_in[0];
    const int*   cnt = (const int*)  d_in[1];
    const float* w1  = (const float*)d_in[2];
    const float* w2  = (const float*)d_in[3];
    const float* w3  = (const float*)d_in[4];
    float* out = (float*)d_out;

    void *pxh, *pw1h, *pw3h, *pw2h;
    cudaGetSymbolAddress(&pxh,  g_xh);
    cudaGetSymbolAddress(&pw1h, g_w1h);
    cudaGetSymbolAddress(&pw3h, g_w3h);
    cudaGetSymbolAddress(&pw2h, g_w2h);

    constexpr int S1 = 4, S2 = 4;
    const int smem1 = 3 * S1 * TILEA;               // 196608 B (A + B0 + B1)
    const int smem2 = S2 * (TILEA + 256 * 128);     // 196608 B (A + wide B0)
    cudaFuncSetAttribute(moe_hmm<1, S1>, cudaFuncAttributeMaxDynamicSharedMemorySize, smem1);
    cudaFuncSetAttribute(moe_hmm<2, S2>, cudaFuncAttributeMaxDynamicSharedMemorySize, smem2);

    // fp16-round x + all three weight tensors in ONE launch.
    const int n4x = TT * DD / 4;
    const int n4w = NUM_E * HH * DD / 4;
    round_pack<<<2048, 256>>>((const float4*)x,  (uint2*)pxh,
                              (const float4*)w1, (uint2*)pw1h,
                              (const float4*)w3, (uint2*)pw3h,
                              (const float4*)w2, (uint2*)pw2h, n4x, n4w);

    moe_hmm<1, S1><<<dim3(HH / 128, TT / BM), NTHREADS, smem1>>>(cnt, nullptr); // (8,128)
    moe_hmm<2, S2><<<dim3(DD / 256, TT / BM), NTHREADS, smem2>>>(cnt, out);     // (8,128)
}